// round 13
// baseline (speedup 1.0000x reference)
#include <cuda_runtime.h>
#include <cuda_bf16.h>
#include <math.h>
#include <stdint.h>

// Problem constants
#define B_SZ 4
#define SEQ  2048
#define DM   1024
#define NH   16
#define DH   64
#define NTOK (B_SZ * SEQ)   // 8192

// ---------------------------------------------------------------------------
// Scratch (device globals).
// g_Q/g_K: tf32 bits, [B,H,S, p8(dh)]  (Q pre-scaled by 0.125*log2e)
// g_V:     tf32 bits, [B,H, S/64, dh, p8(s%64)]
// g_ctx:   tf32 bits  [B*S, DM]
// g_xt:    tf32 bits of x;  g_Wt: tf32 bits of Wq,Wk,Wv,Wo
// ---------------------------------------------------------------------------
__device__ uint32_t g_Q[(size_t)B_SZ * NH * SEQ * DH];
__device__ uint32_t g_K[(size_t)B_SZ * NH * SEQ * DH];
__device__ uint32_t g_V[(size_t)B_SZ * NH * SEQ * DH];
__device__ uint32_t g_ctx[(size_t)NTOK * DM];
__device__ uint32_t g_xt[(size_t)NTOK * DM];
__device__ uint32_t g_Wt[(size_t)4 * DM * DM];

#define QSCALE 0.180336880f   // 0.125 * log2(e): softmax in log2 domain

__device__ __forceinline__ int p8(int k) {
    return (k & ~7) + ((k & 3) << 1) + ((k >> 2) & 1);
}
__device__ __forceinline__ uint32_t rn_tf32(float x) {
    uint32_t r;
    asm("cvt.rna.tf32.f32 %0, %1;" : "=r"(r) : "f"(x));
    return r;
}
__device__ __forceinline__ float ex2(float x) {
    float y;
    asm("ex2.approx.f32 %0, %1;" : "=f"(y) : "f"(x));
    return y;
}
__device__ __forceinline__ uint32_t smem_u32(const void* p) {
    uint32_t a;
    asm("{ .reg .u64 t; cvta.to.shared.u64 t, %1; cvt.u32.u64 %0, t; }"
        : "=r"(a) : "l"(p));
    return a;
}
__device__ __forceinline__ void mma_tf32(float* c, const uint32_t* a,
                                         uint32_t b0, uint32_t b1) {
    asm volatile(
        "mma.sync.aligned.m16n8k8.row.col.f32.tf32.tf32.f32 "
        "{%0,%1,%2,%3}, {%4,%5,%6,%7}, {%8,%9}, {%0,%1,%2,%3};"
        : "+f"(c[0]), "+f"(c[1]), "+f"(c[2]), "+f"(c[3])
        : "r"(a[0]), "r"(a[1]), "r"(a[2]), "r"(a[3]), "r"(b0), "r"(b1));
}

#define CP16(dst32, src) \
    asm volatile("cp.async.cg.shared.global [%0], [%1], 16;" \
                 :: "r"(dst32), "l"(src) : "memory")
#define CP_COMMIT() asm volatile("cp.async.commit_group;" ::: "memory")
#define CP_WAIT0()  asm volatile("cp.async.wait_group 0;" ::: "memory")

// ---------------------------------------------------------------------------
// Prep (single launch): x and the 4 weights -> tf32 bits (rna).
// ---------------------------------------------------------------------------
#define NX  ((size_t)NTOK * DM)      // 8388608
#define NW  ((size_t)DM * DM)        // 1048576

__global__ __launch_bounds__(256) void prep_all(
    const float* __restrict__ x,
    const float* __restrict__ Wq, const float* __restrict__ Wk,
    const float* __restrict__ Wv, const float* __restrict__ Wo,
    uint32_t* __restrict__ xt, uint32_t* __restrict__ Wt)
{
    size_t i = ((size_t)blockIdx.x * 256 + threadIdx.x) * 4;
    const float* src;
    uint32_t* dst;
    size_t off;
    if (i < NX) {
        src = x; dst = xt; off = i;
    } else {
        size_t j = i - NX;
        int w = (int)(j / NW);
        off = j % NW;
        src = (w == 0) ? Wq : (w == 1) ? Wk : (w == 2) ? Wv : Wo;
        dst = Wt + (size_t)w * NW;
    }
    float4 v = *(const float4*)&src[off];
    *(uint4*)&dst[off] = make_uint4(rn_tf32(v.x), rn_tf32(v.y),
                                    rn_tf32(v.z), rn_tf32(v.w));
}

// ---------------------------------------------------------------------------
// TF32 mma GEMM: BM=256, BN=128, BK=32; 512 thr = 4(M) x 4(N) warps;
// per-warp 64x32 (R8-validated fragment addressing). Double-buffered
// cp.async, one barrier per chunk. L2 traffic: 48KB per 1024 mma per CTA.
// mode 0: fp32 out [M,DM] | 1: Q (xQSCALE, p8) | 2: K (p8) | 3: V transposed
// ---------------------------------------------------------------------------
#define AS_U (256 * 36)      // 9216
#define BS_U (32 * 136)      // 4352
#define GEMM_SMEM ((AS_U + BS_U) * 2 * 4)    // 108544 B

__device__ __forceinline__ void gemm_body(
    const uint32_t* __restrict__ A, const uint32_t* __restrict__ W,
    const float* __restrict__ bias, void* __restrict__ outv, int mode)
{
    extern __shared__ uint32_t gsm[];
    const int tid  = threadIdx.x;
    const int warp = tid >> 5, lane = tid & 31;
    const int wm = warp >> 2, wn = warp & 3;
    const int g  = lane >> 2, tig = lane & 3;
    const int m0 = blockIdx.y * 256;
    const int n0 = blockIdx.x * 128;
    const uint32_t sb = smem_u32(gsm);

    float acc[4][4][4];
#pragma unroll
    for (int mt = 0; mt < 4; ++mt)
#pragma unroll
        for (int nt = 0; nt < 4; ++nt)
#pragma unroll
            for (int r = 0; r < 4; ++r) acc[mt][nt][r] = 0.f;

    auto issue_chunk = [&](int c) {
        const int k0 = c * 32;
        const uint32_t ab = sb + ((c & 1) * AS_U) * 4;
        const uint32_t bb = sb + (2 * AS_U + (c & 1) * BS_U) * 4;
#pragma unroll
        for (int i = 0; i < 4; ++i) {
            int it = i * 512 + tid;
            int r = it >> 3, c4 = it & 7;
            CP16(ab + (r * 36 + c4 * 4) * 4,
                 &A[(size_t)(m0 + r) * DM + k0 + c4 * 4]);
        }
#pragma unroll
        for (int i = 0; i < 2; ++i) {
            int it = i * 512 + tid;
            int k = it >> 5, n4 = it & 31;
            CP16(bb + (k * 136 + n4 * 4) * 4,
                 &W[(size_t)(k0 + k) * DM + n0 + n4 * 4]);
        }
    };

    issue_chunk(0);
    CP_COMMIT();

    for (int c = 0; c < 32; ++c) {
        CP_WAIT0();
        __syncthreads();
        if (c + 1 < 32) { issue_chunk(c + 1); CP_COMMIT(); }

        const uint32_t* As = gsm + (c & 1) * AS_U;
        const uint32_t* Bs = gsm + 2 * AS_U + (c & 1) * BS_U;
#pragma unroll
        for (int kk = 0; kk < 32; kk += 8) {
            uint32_t a[4][4], b[4][2];
#pragma unroll
            for (int mt = 0; mt < 4; ++mt) {
                int row = wm * 64 + mt * 16;
                a[mt][0] = As[(row + g    ) * 36 + kk + tig];
                a[mt][1] = As[(row + g + 8) * 36 + kk + tig];
                a[mt][2] = As[(row + g    ) * 36 + kk + tig + 4];
                a[mt][3] = As[(row + g + 8) * 36 + kk + tig + 4];
            }
#pragma unroll
            for (int nt = 0; nt < 4; ++nt) {
                int coln = wn * 32 + nt * 8 + g;
                b[nt][0] = Bs[(kk + tig    ) * 136 + coln];
                b[nt][1] = Bs[(kk + tig + 4) * 136 + coln];
            }
#pragma unroll
            for (int mt = 0; mt < 4; ++mt)
#pragma unroll
                for (int nt = 0; nt < 4; ++nt)
                    mma_tf32(acc[mt][nt], a[mt], b[nt][0], b[nt][1]);
        }
    }

#pragma unroll
    for (int mt = 0; mt < 4; ++mt) {
#pragma unroll
        for (int nt = 0; nt < 4; ++nt) {
            int col  = n0 + wn * 32 + nt * 8 + 2 * tig;
            float2 bv = *(const float2*)&bias[col];
#pragma unroll
            for (int hh = 0; hh < 2; ++hh) {
                int t = m0 + wm * 64 + mt * 16 + g + hh * 8;
                float ox = acc[mt][nt][hh * 2 + 0] + bv.x;
                float oy = acc[mt][nt][hh * 2 + 1] + bv.y;
                if (mode == 0) {
                    *(float2*)&((float*)outv)[(size_t)t * DM + col] =
                        make_float2(ox, oy);
                } else {
                    int bidx = t >> 11;
                    int srow = t & (SEQ - 1);
                    int head = col >> 6;
                    int dh   = col & (DH - 1);
                    uint32_t* dst = (uint32_t*)outv;
                    size_t hb = (size_t)(bidx * NH + head) * SEQ * DH;
                    if (mode != 3) {
                        float sc = (mode == 1) ? QSCALE : 1.0f;
                        dst[hb + (size_t)srow * DH + p8(dh)] =
                            rn_tf32(ox * sc);
                        dst[hb + (size_t)srow * DH + p8(dh + 1)] =
                            rn_tf32(oy * sc);
                    } else {
                        size_t base = hb + (size_t)(srow >> 6) * (DH * 64)
                                      + p8(srow & 63);
                        dst[base + (size_t)dh * 64]       = rn_tf32(ox);
                        dst[base + (size_t)(dh + 1) * 64] = rn_tf32(oy);
                    }
                }
            }
        }
    }
}

__global__ __launch_bounds__(512, 1) void qkv_gemm(
    const uint32_t* __restrict__ xt, const uint32_t* __restrict__ Wt,
    const float* __restrict__ bq, const float* __restrict__ bk,
    const float* __restrict__ bv,
    uint32_t* __restrict__ Qo, uint32_t* __restrict__ Ko,
    uint32_t* __restrict__ Vo)
{
    const int z = blockIdx.z;
    const uint32_t* W = Wt + (size_t)z * DM * DM;
    const float* bias = (z == 0) ? bq : (z == 1) ? bk : bv;
    void* out = (z == 0) ? (void*)Qo : (z == 1) ? (void*)Ko : (void*)Vo;
    gemm_body(xt, W, bias, out, z + 1);
}

__global__ __launch_bounds__(512, 1) void o_gemm(
    const uint32_t* __restrict__ ctx, const uint32_t* __restrict__ Wt,
    const float* __restrict__ bo, float* __restrict__ out)
{
    gemm_body(ctx, Wt + (size_t)3 * DM * DM, bo, out, 0);
}

// ---------------------------------------------------------------------------
// TF32 mma flash attention (R12 structure; softmax in log2 domain via ex2).
// ---------------------------------------------------------------------------
#define KS_STR 72
#define VS_STR 72
#define PS_STR 76
#define PS_U32 (128 * PS_STR)          // 9728
#define KS_U32 (64 * KS_STR)           // 4608
#define KV_U32 (2 * KS_U32)            // 9216 per buffer (K + V)
#define FLASH_SMEM ((PS_U32 + 2 * KV_U32) * 4)   // 112640 B

__global__ __launch_bounds__(128, 2) void flash_mma(
    const uint32_t* __restrict__ Q, const uint32_t* __restrict__ K,
    const uint32_t* __restrict__ V)
{
    extern __shared__ uint32_t sm4[];
    uint32_t* Ps = sm4;
    const uint32_t sb = smem_u32(sm4);

    const int tid  = threadIdx.x;
    const int warp = tid >> 5, lane = tid & 31;
    const int g    = lane >> 2;
    const int tig  = lane & 3;
    const int qt = blockIdx.x;
    const int h  = blockIdx.y;
    const int b  = blockIdx.z;

    const size_t head_off = (size_t)(b * NH + h) * SEQ * DH;
    const uint32_t* Qg = Q + head_off + (size_t)qt * 128 * DH;
    const uint32_t* Kg = K + head_off;
    const uint32_t* Vg = V + head_off;

    auto issue_kv = [&](int kb) {
        const uint32_t kbase = sb + (PS_U32 + (kb & 1) * KV_U32) * 4;
        const uint32_t vbase = kbase + KS_U32 * 4;
#pragma unroll
        for (int i = 0; i < 8; ++i) {
            int it = i * 128 + tid;
            int r = it >> 4, c4 = (it & 15) * 4;
            CP16(kbase + (r * KS_STR + c4) * 4,
                 &Kg[(size_t)(kb * 64 + r) * DH + c4]);
            CP16(vbase + (r * VS_STR + c4) * 4,
                 &Vg[(size_t)kb * (DH * 64) + r * 64 + c4]);
        }
    };

    issue_kv(0);
    CP_COMMIT();

    uint32_t qf[2][8][4];
#pragma unroll
    for (int mt = 0; mt < 2; ++mt) {
        const int row = warp * 32 + mt * 16 + g;
#pragma unroll
        for (int kk = 0; kk < 8; ++kk) {
            uint2 q02 = *(const uint2*)&Qg[(size_t)row * DH + kk * 8 + 2 * tig];
            uint2 q13 = *(const uint2*)&Qg[(size_t)(row + 8) * DH + kk * 8 + 2 * tig];
            qf[mt][kk][0] = q02.x; qf[mt][kk][2] = q02.y;
            qf[mt][kk][1] = q13.x; qf[mt][kk][3] = q13.y;
        }
    }

    float o[2][8][4];
#pragma unroll
    for (int mt = 0; mt < 2; ++mt)
#pragma unroll
        for (int nt = 0; nt < 8; ++nt)
#pragma unroll
            for (int r = 0; r < 4; ++r) o[mt][nt][r] = 0.f;
    float m[2][2], l[2][2];
#pragma unroll
    for (int mt = 0; mt < 2; ++mt) {
        m[mt][0] = m[mt][1] = -1e30f;
        l[mt][0] = l[mt][1] = 0.f;
    }

    for (int kb = 0; kb < SEQ / 64; ++kb) {
        CP_WAIT0();
        __syncthreads();
        if (kb + 1 < SEQ / 64) { issue_kv(kb + 1); CP_COMMIT(); }

        const uint32_t* Ks = sm4 + PS_U32 + (kb & 1) * KV_U32;
        const uint32_t* Vs = Ks + KS_U32;

        float s[2][8][4];
#pragma unroll
        for (int mt = 0; mt < 2; ++mt)
#pragma unroll
            for (int nt = 0; nt < 8; ++nt)
#pragma unroll
                for (int r = 0; r < 4; ++r) s[mt][nt][r] = 0.f;
#pragma unroll
        for (int kk = 0; kk < 8; ++kk) {
#pragma unroll
            for (int nt = 0; nt < 8; ++nt) {
                uint2 bb = *(const uint2*)
                    &Ks[(nt * 8 + g) * KS_STR + kk * 8 + 2 * tig];
                mma_tf32(s[0][nt], qf[0][kk], bb.x, bb.y);
                mma_tf32(s[1][nt], qf[1][kk], bb.x, bb.y);
            }
        }

        // Online softmax in log2 domain (scores pre-scaled by log2e)
#pragma unroll
        for (int mt = 0; mt < 2; ++mt) {
            float mx0 = -1e30f, mx1 = -1e30f;
#pragma unroll
            for (int nt = 0; nt < 8; ++nt) {
                mx0 = fmaxf(mx0, fmaxf(s[mt][nt][0], s[mt][nt][1]));
                mx1 = fmaxf(mx1, fmaxf(s[mt][nt][2], s[mt][nt][3]));
            }
#pragma unroll
            for (int off = 1; off < 4; off <<= 1) {
                mx0 = fmaxf(mx0, __shfl_xor_sync(0xffffffffu, mx0, off, 4));
                mx1 = fmaxf(mx1, __shfl_xor_sync(0xffffffffu, mx1, off, 4));
            }
            float mn0 = fmaxf(m[mt][0], mx0), mn1 = fmaxf(m[mt][1], mx1);
            float c0 = ex2(m[mt][0] - mn0), c1 = ex2(m[mt][1] - mn1);
            m[mt][0] = mn0; m[mt][1] = mn1;

            float sum0 = 0.f, sum1 = 0.f;
            const int row = warp * 32 + mt * 16 + g;
#pragma unroll
            for (int nt = 0; nt < 8; ++nt) {
                s[mt][nt][0] = ex2(s[mt][nt][0] - mn0);
                s[mt][nt][1] = ex2(s[mt][nt][1] - mn0);
                s[mt][nt][2] = ex2(s[mt][nt][2] - mn1);
                s[mt][nt][3] = ex2(s[mt][nt][3] - mn1);
                sum0 += s[mt][nt][0] + s[mt][nt][1];
                sum1 += s[mt][nt][2] + s[mt][nt][3];
                *(uint2*)&Ps[row * PS_STR + nt * 8 + 2 * tig] =
                    make_uint2(rn_tf32(s[mt][nt][0]), rn_tf32(s[mt][nt][1]));
                *(uint2*)&Ps[(row + 8) * PS_STR + nt * 8 + 2 * tig] =
                    make_uint2(rn_tf32(s[mt][nt][2]), rn_tf32(s[mt][nt][3]));
            }
#pragma unroll
            for (int off = 1; off < 4; off <<= 1) {
                sum0 += __shfl_xor_sync(0xffffffffu, sum0, off, 4);
                sum1 += __shfl_xor_sync(0xffffffffu, sum1, off, 4);
            }
            l[mt][0] = l[mt][0] * c0 + sum0;
            l[mt][1] = l[mt][1] * c1 + sum1;
#pragma unroll
            for (int nt = 0; nt < 8; ++nt) {
                o[mt][nt][0] *= c0; o[mt][nt][1] *= c0;
                o[mt][nt][2] *= c1; o[mt][nt][3] *= c1;
            }
        }
        __syncwarp();

#pragma unroll
        for (int kk = 0; kk < 8; ++kk) {
            uint32_t a0[4], a1[4];
            const int r0 = warp * 32 + g;
            a0[0] = Ps[r0 * PS_STR + kk * 8 + tig];
            a0[1] = Ps[(r0 + 8) * PS_STR + kk * 8 + tig];
            a0[2] = Ps[r0 * PS_STR + kk * 8 + tig + 4];
            a0[3] = Ps[(r0 + 8) * PS_STR + kk * 8 + tig + 4];
            a1[0] = Ps[(r0 + 16) * PS_STR + kk * 8 + tig];
            a1[1] = Ps[(r0 + 24) * PS_STR + kk * 8 + tig];
            a1[2] = Ps[(r0 + 16) * PS_STR + kk * 8 + tig + 4];
            a1[3] = Ps[(r0 + 24) * PS_STR + kk * 8 + tig + 4];
#pragma unroll
            for (int nt = 0; nt < 8; ++nt) {
                uint2 bb = *(const uint2*)
                    &Vs[(nt * 8 + g) * VS_STR + kk * 8 + 2 * tig];
                mma_tf32(o[0][nt], a0, bb.x, bb.y);
                mma_tf32(o[1][nt], a1, bb.x, bb.y);
            }
        }
    }

#pragma unroll
    for (int mt = 0; mt < 2; ++mt) {
        const float inv0 = 1.f / l[mt][0], inv1 = 1.f / l[mt][1];
        const int row0 = qt * 128 + warp * 32 + mt * 16 + g;
#pragma unroll
        for (int nt = 0; nt < 8; ++nt) {
            int col = h * DH + nt * 8 + 2 * tig;
            *(uint2*)&g_ctx[(size_t)(b * SEQ + row0) * DM + col] =
                make_uint2(rn_tf32(o[mt][nt][0] * inv0),
                           rn_tf32(o[mt][nt][1] * inv0));
            *(uint2*)&g_ctx[(size_t)(b * SEQ + row0 + 8) * DM + col] =
                make_uint2(rn_tf32(o[mt][nt][2] * inv1),
                           rn_tf32(o[mt][nt][3] * inv1));
        }
    }
}

// ---------------------------------------------------------------------------
// Launch
// ---------------------------------------------------------------------------
extern "C" void kernel_launch(void* const* d_in, const int* in_sizes, int n_in,
                              void* d_out, int out_size)
{
    const float* x  = (const float*)d_in[0];
    const float* Wq = (const float*)d_in[1];
    const float* bq = (const float*)d_in[2];
    const float* Wk = (const float*)d_in[3];
    const float* bk = (const float*)d_in[4];
    const float* Wv = (const float*)d_in[5];
    const float* bv = (const float*)d_in[6];
    const float* Wo = (const float*)d_in[7];
    const float* bo = (const float*)d_in[8];
    float* out = (float*)d_out;

    uint32_t *Qp, *Kp, *Vp, *Cp, *Xp, *Wp;
    cudaGetSymbolAddress((void**)&Qp, g_Q);
    cudaGetSymbolAddress((void**)&Kp, g_K);
    cudaGetSymbolAddress((void**)&Vp, g_V);
    cudaGetSymbolAddress((void**)&Cp, g_ctx);
    cudaGetSymbolAddress((void**)&Xp, g_xt);
    cudaGetSymbolAddress((void**)&Wp, g_Wt);

    cudaFuncSetAttribute(flash_mma,
                         cudaFuncAttributeMaxDynamicSharedMemorySize, FLASH_SMEM);
    cudaFuncSetAttribute(qkv_gemm,
                         cudaFuncAttributeMaxDynamicSharedMemorySize, GEMM_SMEM);
    cudaFuncSetAttribute(o_gemm,
                         cudaFuncAttributeMaxDynamicSharedMemorySize, GEMM_SMEM);

    // Prep: x + 4 weights -> tf32 bits, one launch
    prep_all<<<(int)((NX + 4 * NW) / 1024), 256>>>(x, Wq, Wk, Wv, Wo, Xp, Wp);

    qkv_gemm<<<dim3(DM / 128, NTOK / 256, 3), 512, GEMM_SMEM>>>(
        Xp, Wp, bq, bk, bv, Qp, Kp, Vp);

    flash_mma<<<dim3(SEQ / 128, NH, B_SZ), 128, FLASH_SMEM>>>(Qp, Kp, Vp);

    o_gemm<<<dim3(DM / 128, NTOK / 256), 512, GEMM_SMEM>>>(Cp, Wp, bo, out);
}

// round 14
// speedup vs baseline: 1.0741x; 1.0741x over previous
#include <cuda_runtime.h>
#include <cuda_bf16.h>
#include <math.h>
#include <stdint.h>

// Problem constants
#define B_SZ 4
#define SEQ  2048
#define DM   1024
#define NH   16
#define DH   64
#define NTOK (B_SZ * SEQ)   // 8192

// ---------------------------------------------------------------------------
// Scratch (device globals).
// g_Q/g_K: tf32 bits, [B,H,S, p8(dh)]  (Q pre-scaled by 0.125*log2e)
// g_V:     tf32 bits, [B,H, S/64, dh, p8(s%64)]
// g_ctx:   tf32 bits  [B*S, DM]
// g_xt:    tf32 bits of x;  g_Wt: tf32 bits of Wq,Wk,Wv,Wo
// ---------------------------------------------------------------------------
__device__ uint32_t g_Q[(size_t)B_SZ * NH * SEQ * DH];
__device__ uint32_t g_K[(size_t)B_SZ * NH * SEQ * DH];
__device__ uint32_t g_V[(size_t)B_SZ * NH * SEQ * DH];
__device__ uint32_t g_ctx[(size_t)NTOK * DM];
__device__ uint32_t g_xt[(size_t)NTOK * DM];
__device__ uint32_t g_Wt[(size_t)4 * DM * DM];

#define QSCALE 0.180336880f   // 0.125 * log2(e): softmax in log2 domain

__device__ __forceinline__ int p8(int k) {
    return (k & ~7) + ((k & 3) << 1) + ((k >> 2) & 1);
}
__device__ __forceinline__ uint32_t rn_tf32(float x) {
    uint32_t r;
    asm("cvt.rna.tf32.f32 %0, %1;" : "=r"(r) : "f"(x));
    return r;
}
__device__ __forceinline__ float ex2(float x) {
    float y;
    asm("ex2.approx.f32 %0, %1;" : "=f"(y) : "f"(x));
    return y;
}
__device__ __forceinline__ uint32_t smem_u32(const void* p) {
    uint32_t a;
    asm("{ .reg .u64 t; cvta.to.shared.u64 t, %1; cvt.u32.u64 %0, t; }"
        : "=r"(a) : "l"(p));
    return a;
}
__device__ __forceinline__ void mma_tf32(float* c, const uint32_t* a,
                                         uint32_t b0, uint32_t b1) {
    asm volatile(
        "mma.sync.aligned.m16n8k8.row.col.f32.tf32.tf32.f32 "
        "{%0,%1,%2,%3}, {%4,%5,%6,%7}, {%8,%9}, {%0,%1,%2,%3};"
        : "+f"(c[0]), "+f"(c[1]), "+f"(c[2]), "+f"(c[3])
        : "r"(a[0]), "r"(a[1]), "r"(a[2]), "r"(a[3]), "r"(b0), "r"(b1));
}

#define CP16(dst32, src) \
    asm volatile("cp.async.cg.shared.global [%0], [%1], 16;" \
                 :: "r"(dst32), "l"(src) : "memory")
#define CP_COMMIT() asm volatile("cp.async.commit_group;" ::: "memory")
#define CP_WAIT0()  asm volatile("cp.async.wait_group 0;" ::: "memory")

// ---------------------------------------------------------------------------
// Prep (single launch): x and the 4 weights -> tf32 bits (rna).
// ---------------------------------------------------------------------------
#define NX  ((size_t)NTOK * DM)      // 8388608
#define NW  ((size_t)DM * DM)        // 1048576

__global__ __launch_bounds__(256) void prep_all(
    const float* __restrict__ x,
    const float* __restrict__ Wq, const float* __restrict__ Wk,
    const float* __restrict__ Wv, const float* __restrict__ Wo,
    uint32_t* __restrict__ xt, uint32_t* __restrict__ Wt)
{
    size_t i = ((size_t)blockIdx.x * 256 + threadIdx.x) * 4;
    const float* src;
    uint32_t* dst;
    size_t off;
    if (i < NX) {
        src = x; dst = xt; off = i;
    } else {
        size_t j = i - NX;
        int w = (int)(j / NW);
        off = j % NW;
        src = (w == 0) ? Wq : (w == 1) ? Wk : (w == 2) ? Wv : Wo;
        dst = Wt + (size_t)w * NW;
    }
    float4 v = *(const float4*)&src[off];
    *(uint4*)&dst[off] = make_uint4(rn_tf32(v.x), rn_tf32(v.y),
                                    rn_tf32(v.z), rn_tf32(v.w));
}

// ---------------------------------------------------------------------------
// TF32 mma GEMM (R12-validated shape): BM=128, BN=128, BK=32; 256 thr =
// 2(M) x 4(N) warps; per-warp 64x32. Double-buffered cp.async, one barrier
// per chunk. __launch_bounds__(256,2) pins regs so 2 CTAs/SM are guaranteed.
// mode 0: fp32 out [M,DM] | 1: Q (xQSCALE, p8) | 2: K (p8) | 3: V transposed
// ---------------------------------------------------------------------------
#define AS_U 4608            // 128*36
#define BS_U 4352            // 32*136
#define GEMM_SMEM ((2 * AS_U + 2 * BS_U) * 4)    // 71680 B

__device__ __forceinline__ void gemm_body(
    const uint32_t* __restrict__ A, const uint32_t* __restrict__ W,
    const float* __restrict__ bias, void* __restrict__ outv, int mode)
{
    extern __shared__ uint32_t gsm[];
    const int tid  = threadIdx.x;
    const int warp = tid >> 5, lane = tid & 31;
    const int wm = warp >> 2, wn = warp & 3;
    const int g  = lane >> 2, tig = lane & 3;
    const int m0 = blockIdx.y * 128;
    const int n0 = blockIdx.x * 128;
    const uint32_t sb = smem_u32(gsm);

    float acc[4][4][4];
#pragma unroll
    for (int mt = 0; mt < 4; ++mt)
#pragma unroll
        for (int nt = 0; nt < 4; ++nt)
#pragma unroll
            for (int r = 0; r < 4; ++r) acc[mt][nt][r] = 0.f;

    auto issue_chunk = [&](int c) {
        const int k0 = c * 32;
        const uint32_t ab = sb + ((c & 1) * AS_U) * 4;
        const uint32_t bb = sb + (2 * AS_U + (c & 1) * BS_U) * 4;
#pragma unroll
        for (int i = 0; i < 4; ++i) {
            int it = i * 256 + tid;
            int r = it >> 3, c4 = it & 7;
            CP16(ab + (r * 36 + c4 * 4) * 4,
                 &A[(size_t)(m0 + r) * DM + k0 + c4 * 4]);
        }
#pragma unroll
        for (int i = 0; i < 4; ++i) {
            int it = i * 256 + tid;
            int k = it >> 5, n4 = it & 31;
            CP16(bb + (k * 136 + n4 * 4) * 4,
                 &W[(size_t)(k0 + k) * DM + n0 + n4 * 4]);
        }
    };

    issue_chunk(0);
    CP_COMMIT();

    for (int c = 0; c < 32; ++c) {
        CP_WAIT0();
        __syncthreads();
        if (c + 1 < 32) { issue_chunk(c + 1); CP_COMMIT(); }

        const uint32_t* As = gsm + (c & 1) * AS_U;
        const uint32_t* Bs = gsm + 2 * AS_U + (c & 1) * BS_U;
#pragma unroll
        for (int kk = 0; kk < 32; kk += 8) {
            uint32_t a[4][4], b[4][2];
#pragma unroll
            for (int mt = 0; mt < 4; ++mt) {
                int row = wm * 64 + mt * 16;
                a[mt][0] = As[(row + g    ) * 36 + kk + tig];
                a[mt][1] = As[(row + g + 8) * 36 + kk + tig];
                a[mt][2] = As[(row + g    ) * 36 + kk + tig + 4];
                a[mt][3] = As[(row + g + 8) * 36 + kk + tig + 4];
            }
#pragma unroll
            for (int nt = 0; nt < 4; ++nt) {
                int coln = wn * 32 + nt * 8 + g;
                b[nt][0] = Bs[(kk + tig    ) * 136 + coln];
                b[nt][1] = Bs[(kk + tig + 4) * 136 + coln];
            }
#pragma unroll
            for (int mt = 0; mt < 4; ++mt)
#pragma unroll
                for (int nt = 0; nt < 4; ++nt)
                    mma_tf32(acc[mt][nt], a[mt], b[nt][0], b[nt][1]);
        }
    }

#pragma unroll
    for (int mt = 0; mt < 4; ++mt) {
#pragma unroll
        for (int nt = 0; nt < 4; ++nt) {
            int col  = n0 + wn * 32 + nt * 8 + 2 * tig;
            float2 bv = *(const float2*)&bias[col];
#pragma unroll
            for (int hh = 0; hh < 2; ++hh) {
                int t = m0 + wm * 64 + mt * 16 + g + hh * 8;
                float ox = acc[mt][nt][hh * 2 + 0] + bv.x;
                float oy = acc[mt][nt][hh * 2 + 1] + bv.y;
                if (mode == 0) {
                    *(float2*)&((float*)outv)[(size_t)t * DM + col] =
                        make_float2(ox, oy);
                } else {
                    int bidx = t >> 11;
                    int srow = t & (SEQ - 1);
                    int head = col >> 6;
                    int dh   = col & (DH - 1);
                    uint32_t* dst = (uint32_t*)outv;
                    size_t hb = (size_t)(bidx * NH + head) * SEQ * DH;
                    if (mode != 3) {
                        float sc = (mode == 1) ? QSCALE : 1.0f;
                        dst[hb + (size_t)srow * DH + p8(dh)] =
                            rn_tf32(ox * sc);
                        dst[hb + (size_t)srow * DH + p8(dh + 1)] =
                            rn_tf32(oy * sc);
                    } else {
                        size_t base = hb + (size_t)(srow >> 6) * (DH * 64)
                                      + p8(srow & 63);
                        dst[base + (size_t)dh * 64]       = rn_tf32(ox);
                        dst[base + (size_t)(dh + 1) * 64] = rn_tf32(oy);
                    }
                }
            }
        }
    }
}

__global__ __launch_bounds__(256, 2) void qkv_gemm(
    const uint32_t* __restrict__ xt, const uint32_t* __restrict__ Wt,
    const float* __restrict__ bq, const float* __restrict__ bk,
    const float* __restrict__ bv,
    uint32_t* __restrict__ Qo, uint32_t* __restrict__ Ko,
    uint32_t* __restrict__ Vo)
{
    const int z = blockIdx.z;
    const uint32_t* W = Wt + (size_t)z * DM * DM;
    const float* bias = (z == 0) ? bq : (z == 1) ? bk : bv;
    void* out = (z == 0) ? (void*)Qo : (z == 1) ? (void*)Ko : (void*)Vo;
    gemm_body(xt, W, bias, out, z + 1);
}

__global__ __launch_bounds__(256, 2) void o_gemm(
    const uint32_t* __restrict__ ctx, const uint32_t* __restrict__ Wt,
    const float* __restrict__ bo, float* __restrict__ out)
{
    gemm_body(ctx, Wt + (size_t)3 * DM * DM, bo, out, 0);
}

// ---------------------------------------------------------------------------
// TF32 mma flash attention (R12 structure; softmax in log2 domain via ex2).
// ---------------------------------------------------------------------------
#define KS_STR 72
#define VS_STR 72
#define PS_STR 76
#define PS_U32 (128 * PS_STR)          // 9728
#define KS_U32 (64 * KS_STR)           // 4608
#define KV_U32 (2 * KS_U32)            // 9216 per buffer (K + V)
#define FLASH_SMEM ((PS_U32 + 2 * KV_U32) * 4)   // 112640 B

__global__ __launch_bounds__(128, 2) void flash_mma(
    const uint32_t* __restrict__ Q, const uint32_t* __restrict__ K,
    const uint32_t* __restrict__ V)
{
    extern __shared__ uint32_t sm4[];
    uint32_t* Ps = sm4;
    const uint32_t sb = smem_u32(sm4);

    const int tid  = threadIdx.x;
    const int warp = tid >> 5, lane = tid & 31;
    const int g    = lane >> 2;
    const int tig  = lane & 3;
    const int qt = blockIdx.x;
    const int h  = blockIdx.y;
    const int b  = blockIdx.z;

    const size_t head_off = (size_t)(b * NH + h) * SEQ * DH;
    const uint32_t* Qg = Q + head_off + (size_t)qt * 128 * DH;
    const uint32_t* Kg = K + head_off;
    const uint32_t* Vg = V + head_off;

    auto issue_kv = [&](int kb) {
        const uint32_t kbase = sb + (PS_U32 + (kb & 1) * KV_U32) * 4;
        const uint32_t vbase = kbase + KS_U32 * 4;
#pragma unroll
        for (int i = 0; i < 8; ++i) {
            int it = i * 128 + tid;
            int r = it >> 4, c4 = (it & 15) * 4;
            CP16(kbase + (r * KS_STR + c4) * 4,
                 &Kg[(size_t)(kb * 64 + r) * DH + c4]);
            CP16(vbase + (r * VS_STR + c4) * 4,
                 &Vg[(size_t)kb * (DH * 64) + r * 64 + c4]);
        }
    };

    issue_kv(0);
    CP_COMMIT();

    uint32_t qf[2][8][4];
#pragma unroll
    for (int mt = 0; mt < 2; ++mt) {
        const int row = warp * 32 + mt * 16 + g;
#pragma unroll
        for (int kk = 0; kk < 8; ++kk) {
            uint2 q02 = *(const uint2*)&Qg[(size_t)row * DH + kk * 8 + 2 * tig];
            uint2 q13 = *(const uint2*)&Qg[(size_t)(row + 8) * DH + kk * 8 + 2 * tig];
            qf[mt][kk][0] = q02.x; qf[mt][kk][2] = q02.y;
            qf[mt][kk][1] = q13.x; qf[mt][kk][3] = q13.y;
        }
    }

    float o[2][8][4];
#pragma unroll
    for (int mt = 0; mt < 2; ++mt)
#pragma unroll
        for (int nt = 0; nt < 8; ++nt)
#pragma unroll
            for (int r = 0; r < 4; ++r) o[mt][nt][r] = 0.f;
    float m[2][2], l[2][2];
#pragma unroll
    for (int mt = 0; mt < 2; ++mt) {
        m[mt][0] = m[mt][1] = -1e30f;
        l[mt][0] = l[mt][1] = 0.f;
    }

    for (int kb = 0; kb < SEQ / 64; ++kb) {
        CP_WAIT0();
        __syncthreads();
        if (kb + 1 < SEQ / 64) { issue_kv(kb + 1); CP_COMMIT(); }

        const uint32_t* Ks = sm4 + PS_U32 + (kb & 1) * KV_U32;
        const uint32_t* Vs = Ks + KS_U32;

        float s[2][8][4];
#pragma unroll
        for (int mt = 0; mt < 2; ++mt)
#pragma unroll
            for (int nt = 0; nt < 8; ++nt)
#pragma unroll
                for (int r = 0; r < 4; ++r) s[mt][nt][r] = 0.f;
#pragma unroll
        for (int kk = 0; kk < 8; ++kk) {
#pragma unroll
            for (int nt = 0; nt < 8; ++nt) {
                uint2 bb = *(const uint2*)
                    &Ks[(nt * 8 + g) * KS_STR + kk * 8 + 2 * tig];
                mma_tf32(s[0][nt], qf[0][kk], bb.x, bb.y);
                mma_tf32(s[1][nt], qf[1][kk], bb.x, bb.y);
            }
        }

        // Online softmax in log2 domain (scores pre-scaled by log2e)
#pragma unroll
        for (int mt = 0; mt < 2; ++mt) {
            float mx0 = -1e30f, mx1 = -1e30f;
#pragma unroll
            for (int nt = 0; nt < 8; ++nt) {
                mx0 = fmaxf(mx0, fmaxf(s[mt][nt][0], s[mt][nt][1]));
                mx1 = fmaxf(mx1, fmaxf(s[mt][nt][2], s[mt][nt][3]));
            }
#pragma unroll
            for (int off = 1; off < 4; off <<= 1) {
                mx0 = fmaxf(mx0, __shfl_xor_sync(0xffffffffu, mx0, off, 4));
                mx1 = fmaxf(mx1, __shfl_xor_sync(0xffffffffu, mx1, off, 4));
            }
            float mn0 = fmaxf(m[mt][0], mx0), mn1 = fmaxf(m[mt][1], mx1);
            float c0 = ex2(m[mt][0] - mn0), c1 = ex2(m[mt][1] - mn1);
            m[mt][0] = mn0; m[mt][1] = mn1;

            float sum0 = 0.f, sum1 = 0.f;
            const int row = warp * 32 + mt * 16 + g;
#pragma unroll
            for (int nt = 0; nt < 8; ++nt) {
                s[mt][nt][0] = ex2(s[mt][nt][0] - mn0);
                s[mt][nt][1] = ex2(s[mt][nt][1] - mn0);
                s[mt][nt][2] = ex2(s[mt][nt][2] - mn1);
                s[mt][nt][3] = ex2(s[mt][nt][3] - mn1);
                sum0 += s[mt][nt][0] + s[mt][nt][1];
                sum1 += s[mt][nt][2] + s[mt][nt][3];
                *(uint2*)&Ps[row * PS_STR + nt * 8 + 2 * tig] =
                    make_uint2(rn_tf32(s[mt][nt][0]), rn_tf32(s[mt][nt][1]));
                *(uint2*)&Ps[(row + 8) * PS_STR + nt * 8 + 2 * tig] =
                    make_uint2(rn_tf32(s[mt][nt][2]), rn_tf32(s[mt][nt][3]));
            }
#pragma unroll
            for (int off = 1; off < 4; off <<= 1) {
                sum0 += __shfl_xor_sync(0xffffffffu, sum0, off, 4);
                sum1 += __shfl_xor_sync(0xffffffffu, sum1, off, 4);
            }
            l[mt][0] = l[mt][0] * c0 + sum0;
            l[mt][1] = l[mt][1] * c1 + sum1;
#pragma unroll
            for (int nt = 0; nt < 8; ++nt) {
                o[mt][nt][0] *= c0; o[mt][nt][1] *= c0;
                o[mt][nt][2] *= c1; o[mt][nt][3] *= c1;
            }
        }
        __syncwarp();

#pragma unroll
        for (int kk = 0; kk < 8; ++kk) {
            uint32_t a0[4], a1[4];
            const int r0 = warp * 32 + g;
            a0[0] = Ps[r0 * PS_STR + kk * 8 + tig];
            a0[1] = Ps[(r0 + 8) * PS_STR + kk * 8 + tig];
            a0[2] = Ps[r0 * PS_STR + kk * 8 + tig + 4];
            a0[3] = Ps[(r0 + 8) * PS_STR + kk * 8 + tig + 4];
            a1[0] = Ps[(r0 + 16) * PS_STR + kk * 8 + tig];
            a1[1] = Ps[(r0 + 24) * PS_STR + kk * 8 + tig];
            a1[2] = Ps[(r0 + 16) * PS_STR + kk * 8 + tig + 4];
            a1[3] = Ps[(r0 + 24) * PS_STR + kk * 8 + tig + 4];
#pragma unroll
            for (int nt = 0; nt < 8; ++nt) {
                uint2 bb = *(const uint2*)
                    &Vs[(nt * 8 + g) * VS_STR + kk * 8 + 2 * tig];
                mma_tf32(o[0][nt], a0, bb.x, bb.y);
                mma_tf32(o[1][nt], a1, bb.x, bb.y);
            }
        }
    }

#pragma unroll
    for (int mt = 0; mt < 2; ++mt) {
        const float inv0 = 1.f / l[mt][0], inv1 = 1.f / l[mt][1];
        const int row0 = qt * 128 + warp * 32 + mt * 16 + g;
#pragma unroll
        for (int nt = 0; nt < 8; ++nt) {
            int col = h * DH + nt * 8 + 2 * tig;
            *(uint2*)&g_ctx[(size_t)(b * SEQ + row0) * DM + col] =
                make_uint2(rn_tf32(o[mt][nt][0] * inv0),
                           rn_tf32(o[mt][nt][1] * inv0));
            *(uint2*)&g_ctx[(size_t)(b * SEQ + row0 + 8) * DM + col] =
                make_uint2(rn_tf32(o[mt][nt][2] * inv1),
                           rn_tf32(o[mt][nt][3] * inv1));
        }
    }
}

// ---------------------------------------------------------------------------
// Launch
// ---------------------------------------------------------------------------
extern "C" void kernel_launch(void* const* d_in, const int* in_sizes, int n_in,
                              void* d_out, int out_size)
{
    const float* x  = (const float*)d_in[0];
    const float* Wq = (const float*)d_in[1];
    const float* bq = (const float*)d_in[2];
    const float* Wk = (const float*)d_in[3];
    const float* bk = (const float*)d_in[4];
    const float* Wv = (const float*)d_in[5];
    const float* bv = (const float*)d_in[6];
    const float* Wo = (const float*)d_in[7];
    const float* bo = (const float*)d_in[8];
    float* out = (float*)d_out;

    uint32_t *Qp, *Kp, *Vp, *Cp, *Xp, *Wp;
    cudaGetSymbolAddress((void**)&Qp, g_Q);
    cudaGetSymbolAddress((void**)&Kp, g_K);
    cudaGetSymbolAddress((void**)&Vp, g_V);
    cudaGetSymbolAddress((void**)&Cp, g_ctx);
    cudaGetSymbolAddress((void**)&Xp, g_xt);
    cudaGetSymbolAddress((void**)&Wp, g_Wt);

    cudaFuncSetAttribute(flash_mma,
                         cudaFuncAttributeMaxDynamicSharedMemorySize, FLASH_SMEM);
    cudaFuncSetAttribute(qkv_gemm,
                         cudaFuncAttributeMaxDynamicSharedMemorySize, GEMM_SMEM);
    cudaFuncSetAttribute(o_gemm,
                         cudaFuncAttributeMaxDynamicSharedMemorySize, GEMM_SMEM);

    // Prep: x + 4 weights -> tf32 bits, one launch
    prep_all<<<(int)((NX + 4 * NW) / 1024), 256>>>(x, Wq, Wk, Wv, Wo, Xp, Wp);

    qkv_gemm<<<dim3(DM / 128, NTOK / 128, 3), 256, GEMM_SMEM>>>(
        Xp, Wp, bq, bk, bv, Qp, Kp, Vp);

    flash_mma<<<dim3(SEQ / 128, NH, B_SZ), 128, FLASH_SMEM>>>(Qp, Kp, Vp);

    o_gemm<<<dim3(DM / 128, NTOK / 128), 256, GEMM_SMEM>>>(Cp, Wp, bo, out);
}